// round 6
// baseline (speedup 1.0000x reference)
#include <cuda_runtime.h>
#include <cstdint>

#define T_TOK   8192
#define H_DIM   2048
#define I_DIM   4096
#define NE      8
#define LISTCAP 16384
#define MAXTILES 135
#define HM_ROWS  17536
#define QMAX    16256.0f

#define STB     16384          /* bytes per stage: Ah|Al|Bh|Bl planes of 4KB */
#define OFF_AL  4096
#define OFF_BH  8192
#define OFF_BL  12288

// ---------------- device scratch (no allocations allowed) ----------------
__device__ int      g_cnt[NE];
__device__ int      g_base[NE];
__device__ int      g_ntiles;
__device__ int      g_tile_e[MAXTILES];
__device__ int      g_tile_m[MAXTILES];
__device__ int      g_tok[NE * LISTCAP];
__device__ float    g_coef[NE * LISTCAP];

__device__ float    g_sx[T_TOK];
__device__ float    g_sw13[NE * 2 * I_DIM];
__device__ float    g_sw2[NE * H_DIM];
__device__ float    g_shm[HM_ROWS];
__device__ unsigned g_hmax[HM_ROWS];

__device__ int8_t   g_qxh[(size_t)T_TOK * H_DIM];
__device__ int8_t   g_qxl[(size_t)T_TOK * H_DIM];
__device__ int8_t   g_qw13h[(size_t)NE * 2 * I_DIM * H_DIM];
__device__ int8_t   g_qw13l[(size_t)NE * 2 * I_DIM * H_DIM];
__device__ int8_t   g_qw2h[(size_t)NE * H_DIM * I_DIM];
__device__ int8_t   g_qw2l[(size_t)NE * H_DIM * I_DIM];
__device__ float    g_hm[(size_t)HM_ROWS * I_DIM];
__device__ int8_t   g_hmh[(size_t)HM_ROWS * I_DIM];
__device__ int8_t   g_hml[(size_t)HM_ROWS * I_DIM];

// ---------------- helpers ----------------
__device__ __forceinline__ uint32_t smem_u32(const void* p) {
    uint32_t a;
    asm("{ .reg .u64 t; cvta.to.shared.u64 t, %1; cvt.u32.u64 %0, t; }" : "=r"(a) : "l"(p));
    return a;
}

// swizzled offset in a [128 rows][32B] tile: 16B chunk XOR'd with row bit2
#define SWZ16(r, c) ((uint32_t)((r) * 32 + ((((c) ^ (((r) >> 2) & 1))) << 4)))

#define CP16(dst, src) \
    asm volatile("cp.async.cg.shared.global [%0], [%1], 16;" :: "r"(dst), "l"(src))
#define CP_COMMIT() asm volatile("cp.async.commit_group;" ::: "memory")
#define CP_WAIT1()  asm volatile("cp.async.wait_group 1;" ::: "memory")
#define CP_WAIT0()  asm volatile("cp.async.wait_group 0;" ::: "memory")

__device__ __forceinline__ void ldsm4(uint32_t* r, uint32_t addr) {
    asm volatile("ldmatrix.sync.aligned.m8n8.x4.shared.b16 {%0,%1,%2,%3}, [%4];"
                 : "=r"(r[0]), "=r"(r[1]), "=r"(r[2]), "=r"(r[3]) : "r"(addr));
}

__device__ __forceinline__ void mma8(int* c, const uint32_t* a, uint32_t b0, uint32_t b1) {
    asm volatile(
        "mma.sync.aligned.m16n8k32.row.col.s32.s8.s8.s32 "
        "{%0,%1,%2,%3}, {%4,%5,%6,%7}, {%8,%9}, {%0,%1,%2,%3};\n"
        : "+r"(c[0]), "+r"(c[1]), "+r"(c[2]), "+r"(c[3])
        : "r"(a[0]), "r"(a[1]), "r"(a[2]), "r"(a[3]), "r"(b0), "r"(b1));
}

__device__ __forceinline__ float comb(int H, int M) {
    return fmaf(16384.0f, __int2float_rn(H), 128.0f * __int2float_rn(M));
}

__device__ __forceinline__ void quant4(float4 v, float inv, char4& h, char4& l) {
    float q0 = fminf(fmaxf(rintf(v.x * inv), -QMAX), QMAX);
    float q1 = fminf(fmaxf(rintf(v.y * inv), -QMAX), QMAX);
    float q2 = fminf(fmaxf(rintf(v.z * inv), -QMAX), QMAX);
    float q3 = fminf(fmaxf(rintf(v.w * inv), -QMAX), QMAX);
    float h0 = rintf(q0 * 0.0078125f), h1 = rintf(q1 * 0.0078125f);
    float h2 = rintf(q2 * 0.0078125f), h3 = rintf(q3 * 0.0078125f);
    h = make_char4((signed char)(int)h0, (signed char)(int)h1,
                   (signed char)(int)h2, (signed char)(int)h3);
    l = make_char4((signed char)(int)(q0 - 128.0f * h0), (signed char)(int)(q1 - 128.0f * h1),
                   (signed char)(int)(q2 - 128.0f * h2), (signed char)(int)(q3 - 128.0f * h3));
}

// ---------------- small kernels ----------------
__global__ void k_clear(float* __restrict__ out, int n) {
    int i = blockIdx.x * 256 + threadIdx.x;
    if (i < n) out[i] = 0.0f;
    if (i < HM_ROWS) g_hmax[i] = 0u;
}

__global__ void k_route(const int* __restrict__ rt, const float* __restrict__ rw) {
    __shared__ int scnt[NE], scur[NE];
    int tid = threadIdx.x;
    if (tid < NE) scnt[tid] = 0;
    __syncthreads();
    for (int t = tid; t < T_TOK; t += 256) {
        atomicAdd(&scnt[rt[2 * t]], 1);
        atomicAdd(&scnt[rt[2 * t + 1]], 1);
    }
    __syncthreads();
    if (tid == 0) {
        int base = 0, nt = 0;
        for (int e = 0; e < NE; ++e) {
            int c = scnt[e];
            g_cnt[e] = c;
            g_base[e] = base;
            for (int m0 = 0; m0 < c; m0 += 128) {
                g_tile_e[nt] = e;
                g_tile_m[nt] = m0;
                nt++;
            }
            base += (c + 127) / 128 * 128;
        }
        g_ntiles = nt;
    }
    if (tid < NE) scur[tid] = 0;
    __syncthreads();
    for (int t = tid; t < T_TOK; t += 256) {
#pragma unroll
        for (int k = 0; k < 2; ++k) {
            int e = rt[2 * t + k];
            int p = atomicAdd(&scur[e], 1);
            g_tok[e * LISTCAP + p]  = t;
            g_coef[e * LISTCAP + p] = rw[2 * t + k];
        }
    }
}

// warp-per-row quantizers
__global__ void k_qx(const float* __restrict__ x) {
    int row = blockIdx.x * 8 + (threadIdx.x >> 5);
    int lane = threadIdx.x & 31;
    const float4* src = (const float4*)(x + (size_t)row * H_DIM);
    float mx = 0.0f;
    for (int i = lane; i < H_DIM / 4; i += 32) {
        float4 v = src[i];
        mx = fmaxf(mx, fmaxf(fmaxf(fabsf(v.x), fabsf(v.y)), fmaxf(fabsf(v.z), fabsf(v.w))));
    }
#pragma unroll
    for (int o = 16; o; o >>= 1) mx = fmaxf(mx, __shfl_xor_sync(0xffffffffu, mx, o));
    mx = fmaxf(mx, 1e-30f);
    float inv = QMAX / mx;
    if (lane == 0) g_sx[row] = mx / QMAX;
    char4* dh = (char4*)(g_qxh + (size_t)row * H_DIM);
    char4* dl = (char4*)(g_qxl + (size_t)row * H_DIM);
    for (int i = lane; i < H_DIM / 4; i += 32) {
        char4 h, l;
        quant4(src[i], inv, h, l);
        dh[i] = h;
        dl[i] = l;
    }
}

// quantize + permute w13: dst row n (0..8191 per e) = gate j (n even) / up j (n odd)
__global__ void k_qw13(const float* __restrict__ w13) {
    int row = blockIdx.x * 8 + (threadIdx.x >> 5);   // 0 .. NE*8192-1 (permuted)
    int lane = threadIdx.x & 31;
    int e = row >> 13, n = row & 8191;
    int j = n >> 1;
    int srcrow = (n & 1) ? (I_DIM + j) : j;
    const float4* src = (const float4*)(w13 + ((size_t)e * 2 * I_DIM + srcrow) * H_DIM);
    float mx = 0.0f;
    for (int i = lane; i < H_DIM / 4; i += 32) {
        float4 v = src[i];
        mx = fmaxf(mx, fmaxf(fmaxf(fabsf(v.x), fabsf(v.y)), fmaxf(fabsf(v.z), fabsf(v.w))));
    }
#pragma unroll
    for (int o = 16; o; o >>= 1) mx = fmaxf(mx, __shfl_xor_sync(0xffffffffu, mx, o));
    mx = fmaxf(mx, 1e-30f);
    float inv = QMAX / mx;
    if (lane == 0) g_sw13[row] = mx / QMAX;
    char4* dh = (char4*)(g_qw13h + (size_t)row * H_DIM);
    char4* dl = (char4*)(g_qw13l + (size_t)row * H_DIM);
    for (int i = lane; i < H_DIM / 4; i += 32) {
        char4 h, l;
        quant4(src[i], inv, h, l);
        dh[i] = h;
        dl[i] = l;
    }
}

__global__ void k_qw2(const float* __restrict__ w2) {
    int row = blockIdx.x * 8 + (threadIdx.x >> 5);   // 0 .. NE*2048-1
    int lane = threadIdx.x & 31;
    const float4* src = (const float4*)(w2 + (size_t)row * I_DIM);
    float mx = 0.0f;
    for (int i = lane; i < I_DIM / 4; i += 32) {
        float4 v = src[i];
        mx = fmaxf(mx, fmaxf(fmaxf(fabsf(v.x), fabsf(v.y)), fmaxf(fabsf(v.z), fabsf(v.w))));
    }
#pragma unroll
    for (int o = 16; o; o >>= 1) mx = fmaxf(mx, __shfl_xor_sync(0xffffffffu, mx, o));
    mx = fmaxf(mx, 1e-30f);
    float inv = QMAX / mx;
    if (lane == 0) g_sw2[row] = mx / QMAX;
    char4* dh = (char4*)(g_qw2h + (size_t)row * I_DIM);
    char4* dl = (char4*)(g_qw2l + (size_t)row * I_DIM);
    for (int i = lane; i < I_DIM / 4; i += 32) {
        char4 h, l;
        quant4(src[i], inv, h, l);
        dh[i] = h;
        dl[i] = l;
    }
}

// quantize Hm using per-row max gathered by gemm1's atomicMax
__global__ void k_qhm() {
    int row = blockIdx.x * 8 + (threadIdx.x >> 5);   // 0 .. HM_ROWS-1
    int lane = threadIdx.x & 31;
    float mx = fmaxf(__uint_as_float(g_hmax[row]), 1e-30f);
    float inv = QMAX / mx;
    if (lane == 0) g_shm[row] = mx / QMAX;
    const float4* src = (const float4*)(g_hm + (size_t)row * I_DIM);
    char4* dh = (char4*)(g_hmh + (size_t)row * I_DIM);
    char4* dl = (char4*)(g_hml + (size_t)row * I_DIM);
    for (int i = lane; i < I_DIM / 4; i += 32) {
        char4 h, l;
        quant4(src[i], inv, h, l);
        dh[i] = h;
        dl[i] = l;
    }
}

// ---------------- int8 fragment compute core (one K=32 stage) ----------------
__device__ __forceinline__ void compute_stage(uint32_t st, int warp_m, int warp_n, int lane,
                                              int (&aH)[4][4][4], int (&aM)[4][4][4]) {
    const int rsel = lane & 15;
    const int csel = lane >> 4;
    uint32_t bh[2][4], bl[2][4];
#pragma unroll
    for (int p = 0; p < 2; ++p) {
        uint32_t b = st + OFF_BH + SWZ16(warp_n * 32 + p * 16 + rsel, csel);
        ldsm4(bh[p], b);
        ldsm4(bl[p], b + (OFF_BL - OFF_BH));
    }
#pragma unroll
    for (int mf = 0; mf < 4; ++mf) {
        uint32_t ah[4], al[4];
        uint32_t a = st + SWZ16(warp_m * 64 + mf * 16 + rsel, csel);
        ldsm4(ah, a);
        ldsm4(al, a + OFF_AL);
#pragma unroll
        for (int p = 0; p < 2; ++p)
#pragma unroll
            for (int s = 0; s < 2; ++s) {
                int nf = p * 2 + s;
                mma8(aH[mf][nf], ah, bh[p][s], bh[p][s + 2]);
                mma8(aM[mf][nf], ah, bl[p][s], bl[p][s + 2]);
                mma8(aM[mf][nf], al, bh[p][s], bh[p][s + 2]);
            }
    }
}

// ---------------- GEMM1: Xq[gathered] @ W13q^T, SwiGLU -> f32 Hm + row max ------
__global__ __launch_bounds__(256, 1) void k_gemm1() {
    __shared__ __align__(128) char smem[3 * STB];

    const int tid = threadIdx.x, lane = tid & 31, wid = tid >> 5;
    const int warp_m = wid & 1, warp_n = wid >> 1;

    const int tile = blockIdx.y;
    if (tile >= g_ntiles) return;
    const int e   = g_tile_e[tile];
    const int m0  = g_tile_m[tile];
    const int n0  = blockIdx.x * 128;          // over 8192 permuted rows
    const int cnt = g_cnt[e];
    const int* tokp = g_tok + e * LISTCAP;

    const int r = tid >> 1, c = tid & 1;
    int m = m0 + r;
    int tok = (m < cnt) ? tokp[m] : tokp[0];
    const int8_t* sAh = g_qxh + (size_t)tok * H_DIM + c * 16;
    const int8_t* sAl = g_qxl + (size_t)tok * H_DIM + c * 16;
    const size_t brow = ((size_t)e * 2 * I_DIM + n0 + r) * H_DIM + c * 16;
    const int8_t* sBh = g_qw13h + brow;
    const int8_t* sBl = g_qw13l + brow;

    const uint32_t sb = smem_u32(smem);
    const uint32_t dA = SWZ16(r, c);

#define G1_ISSUE(it)                                                         \
    do {                                                                     \
        uint32_t b_ = sb + ((it) % 3) * STB;                                 \
        int k_ = (it) * 32;                                                  \
        CP16(b_ + dA, sAh + k_);                                             \
        CP16(b_ + OFF_AL + dA, sAl + k_);                                    \
        CP16(b_ + OFF_BH + dA, sBh + k_);                                    \
        CP16(b_ + OFF_BL + dA, sBl + k_);                                    \
        CP_COMMIT();                                                         \
    } while (0)

    int aH[4][4][4], aM[4][4][4];
#pragma unroll
    for (int a = 0; a < 4; ++a)
#pragma unroll
        for (int b = 0; b < 4; ++b)
#pragma unroll
            for (int d = 0; d < 4; ++d) { aH[a][b][d] = 0; aM[a][b][d] = 0; }

    const int KT = H_DIM / 32;   // 64
    G1_ISSUE(0);
    G1_ISSUE(1);
#pragma unroll 1
    for (int it = 0; it < KT; ++it) {
        if (it < KT - 1) CP_WAIT1(); else CP_WAIT0();
        __syncthreads();
        if (it + 2 < KT) G1_ISSUE(it + 2);
        compute_stage(sb + (it % 3) * STB, warp_m, warp_n, lane, aH, aM);
    }

    // epilogue: dequant, SwiGLU, write f32 Hm, track row max
    const int gq = lane >> 2, t4 = lane & 3;
    const int rowbase = g_base[e] + m0;
#pragma unroll
    for (int mf = 0; mf < 4; ++mf) {
        int rl = warp_m * 64 + mf * 16 + gq;
        float sxr[2], hmax2[2] = {0.0f, 0.0f};
#pragma unroll
        for (int hh = 0; hh < 2; ++hh) {
            int mm = m0 + rl + 8 * hh;
            int tk = (mm < cnt) ? tokp[mm] : tokp[0];
            sxr[hh] = g_sx[tk];
        }
#pragma unroll
        for (int nf = 0; nf < 4; ++nf) {
            int pn = n0 + warp_n * 32 + nf * 8 + 2 * t4;
            float swg = g_sw13[e * 8192 + pn];
            float swu = g_sw13[e * 8192 + pn + 1];
            int j = pn >> 1;
#pragma unroll
            for (int hh = 0; hh < 2; ++hh) {
                float gg = sxr[hh] * swg * comb(aH[mf][nf][2 * hh], aM[mf][nf][2 * hh]);
                float uu = sxr[hh] * swu * comb(aH[mf][nf][2 * hh + 1], aM[mf][nf][2 * hh + 1]);
                float hv = uu * gg / (1.0f + __expf(-gg));
                g_hm[(size_t)(rowbase + rl + 8 * hh) * I_DIM + j] = hv;
                hmax2[hh] = fmaxf(hmax2[hh], fabsf(hv));
            }
        }
#pragma unroll
        for (int hh = 0; hh < 2; ++hh) {
            float v = hmax2[hh];
            v = fmaxf(v, __shfl_xor_sync(0xffffffffu, v, 1));
            v = fmaxf(v, __shfl_xor_sync(0xffffffffu, v, 2));
            if (t4 == 0) atomicMax(&g_hmax[rowbase + rl + 8 * hh], __float_as_uint(v));
        }
    }
#undef G1_ISSUE
}

// ---------------- GEMM2: Hmq @ W2q^T, coef-scaled atomic scatter -> out ---------
__global__ __launch_bounds__(256, 1) void k_gemm2(float* __restrict__ out) {
    __shared__ __align__(128) char smem[3 * STB];

    const int tid = threadIdx.x, lane = tid & 31, wid = tid >> 5;
    const int warp_m = wid & 1, warp_n = wid >> 1;

    const int tile = blockIdx.y;
    if (tile >= g_ntiles) return;
    const int e   = g_tile_e[tile];
    const int m0  = g_tile_m[tile];
    const int n0  = blockIdx.x * 128;          // over H_DIM
    const int cnt = g_cnt[e];
    const int rb  = g_base[e];

    const int r = tid >> 1, c = tid & 1;
    const size_t arow = (size_t)(rb + m0 + r) * I_DIM + c * 16;
    const int8_t* sAh = g_hmh + arow;
    const int8_t* sAl = g_hml + arow;
    const size_t brow = ((size_t)e * H_DIM + n0 + r) * I_DIM + c * 16;
    const int8_t* sBh = g_qw2h + brow;
    const int8_t* sBl = g_qw2l + brow;

    const uint32_t sb = smem_u32(smem);
    const uint32_t dA = SWZ16(r, c);

#define G2_ISSUE(it)                                                         \
    do {                                                                     \
        uint32_t b_ = sb + ((it) % 3) * STB;                                 \
        int k_ = (it) * 32;                                                  \
        CP16(b_ + dA, sAh + k_);                                             \
        CP16(b_ + OFF_AL + dA, sAl + k_);                                    \
        CP16(b_ + OFF_BH + dA, sBh + k_);                                    \
        CP16(b_ + OFF_BL + dA, sBl + k_);                                    \
        CP_COMMIT();                                                         \
    } while (0)

    int aH[4][4][4], aM[4][4][4];
#pragma unroll
    for (int a = 0; a < 4; ++a)
#pragma unroll
        for (int b = 0; b < 4; ++b)
#pragma unroll
            for (int d = 0; d < 4; ++d) { aH[a][b][d] = 0; aM[a][b][d] = 0; }

    const int KT = I_DIM / 32;   // 128
    G2_ISSUE(0);
    G2_ISSUE(1);
#pragma unroll 1
    for (int it = 0; it < KT; ++it) {
        if (it < KT - 1) CP_WAIT1(); else CP_WAIT0();
        __syncthreads();
        if (it + 2 < KT) G2_ISSUE(it + 2);
        compute_stage(sb + (it % 3) * STB, warp_m, warp_n, lane, aH, aM);
    }

    // epilogue: dequant, coef-scaled atomic scatter
    const int gq = lane >> 2, t4 = lane & 3;
    const int* tokp = g_tok + e * LISTCAP;
    const float* cfp = g_coef + e * LISTCAP;
#pragma unroll
    for (int mf = 0; mf < 4; ++mf) {
        int rl = warp_m * 64 + mf * 16 + gq;
#pragma unroll
        for (int hh = 0; hh < 2; ++hh) {
            int mm = m0 + rl + 8 * hh;
            if (mm < cnt) {
                int tok  = tokp[mm];
                float cs = cfp[mm] * g_shm[rb + mm];
                float* orow = out + (size_t)tok * H_DIM;
#pragma unroll
                for (int nf = 0; nf < 4; ++nf) {
                    int col = n0 + warp_n * 32 + nf * 8 + 2 * t4;
                    float s0 = g_sw2[e * H_DIM + col];
                    float s1 = g_sw2[e * H_DIM + col + 1];
                    atomicAdd(&orow[col],
                              cs * s0 * comb(aH[mf][nf][2 * hh], aM[mf][nf][2 * hh]));
                    atomicAdd(&orow[col + 1],
                              cs * s1 * comb(aH[mf][nf][2 * hh + 1], aM[mf][nf][2 * hh + 1]));
                }
            }
        }
    }
#undef G2_ISSUE
}

// --------------------------------------------------------------------------
extern "C" void kernel_launch(void* const* d_in, const int* in_sizes, int n_in,
                              void* d_out, int out_size) {
    const float* x   = (const float*)d_in[0];
    const int*   rt  = (const int*)d_in[1];
    const float* rw  = (const float*)d_in[2];
    const float* w13 = (const float*)d_in[3];
    const float* w2  = (const float*)d_in[4];
    float* out = (float*)d_out;

    const int n = T_TOK * H_DIM;
    k_clear<<<(n + 255) / 256, 256>>>(out, n);                 // launch 0
    k_route<<<1, 256>>>(rt, rw);                               // launch 1
    k_qx<<<T_TOK / 8, 256>>>(x);                               // launch 2
    k_qw13<<<NE * 2 * I_DIM / 8, 256>>>(w13);                  // launch 3
    k_qw2<<<NE * H_DIM / 8, 256>>>(w2);                        // launch 4
    k_gemm1<<<dim3((2 * I_DIM) / 128, MAXTILES), 256>>>();     // launch 5 (ncu -s 5)
    k_qhm<<<HM_ROWS / 8, 256>>>();                             // launch 6
    k_gemm2<<<dim3(H_DIM / 128, MAXTILES), 256>>>(out);        // launch 7
}

// round 9
// speedup vs baseline: 1.0018x; 1.0018x over previous
#include <cuda_runtime.h>
#include <cstdint>

#define T_TOK   8192
#define H_DIM   2048
#define I_DIM   4096
#define NE      8
#define LISTCAP 16384
#define MAXTILES 135
#define HM_ROWS  17536
#define QMAX    16256.0f

#define STB     16384          /* bytes per stage: Ah|Al|Bh|Bl planes of 4KB */
#define OFF_AL  4096
#define OFF_BH  8192
#define OFF_BL  12288

// ---------------- device scratch (no allocations allowed) ----------------
__device__ int      g_cnt[NE];
__device__ int      g_base[NE];
__device__ int      g_ntiles;
__device__ int      g_tile_e[MAXTILES];
__device__ int      g_tile_m[MAXTILES];
__device__ int      g_tok[NE * LISTCAP];
__device__ float    g_coef[NE * LISTCAP];

__device__ float    g_sx[T_TOK];
__device__ float    g_sw13[NE * 2 * I_DIM];
__device__ float    g_sw2[NE * H_DIM];
__device__ float    g_shm[HM_ROWS];
__device__ unsigned g_hmax[HM_ROWS];

__device__ int8_t   g_qxh[(size_t)T_TOK * H_DIM];
__device__ int8_t   g_qxl[(size_t)T_TOK * H_DIM];
__device__ int8_t   g_qw13h[(size_t)NE * 2 * I_DIM * H_DIM];
__device__ int8_t   g_qw13l[(size_t)NE * 2 * I_DIM * H_DIM];
__device__ int8_t   g_qw2h[(size_t)NE * H_DIM * I_DIM];
__device__ int8_t   g_qw2l[(size_t)NE * H_DIM * I_DIM];
__device__ float    g_hm[(size_t)HM_ROWS * I_DIM];
__device__ int8_t   g_hmh[(size_t)HM_ROWS * I_DIM];
__device__ int8_t   g_hml[(size_t)HM_ROWS * I_DIM];

// ---------------- helpers ----------------
__device__ __forceinline__ uint32_t smem_u32(const void* p) {
    uint32_t a;
    asm("{ .reg .u64 t; cvta.to.shared.u64 t, %1; cvt.u32.u64 %0, t; }" : "=r"(a) : "l"(p));
    return a;
}

// swizzled offset in a [128 rows][32B] tile: 16B chunk XOR'd with row bit2
#define SWZ16(r, c) ((uint32_t)((r) * 32 + ((((c) ^ (((r) >> 2) & 1))) << 4)))

#define CP16(dst, src) \
    asm volatile("cp.async.cg.shared.global [%0], [%1], 16;" :: "r"(dst), "l"(src))
#define CP_COMMIT() asm volatile("cp.async.commit_group;" ::: "memory")
#define CP_WAIT1()  asm volatile("cp.async.wait_group 1;" ::: "memory")
#define CP_WAIT0()  asm volatile("cp.async.wait_group 0;" ::: "memory")

__device__ __forceinline__ void ldsm4(uint32_t* r, uint32_t addr) {
    asm volatile("ldmatrix.sync.aligned.m8n8.x4.shared.b16 {%0,%1,%2,%3}, [%4];"
                 : "=r"(r[0]), "=r"(r[1]), "=r"(r[2]), "=r"(r[3]) : "r"(addr));
}

__device__ __forceinline__ void mma8(int* c, const uint32_t* a, uint32_t b0, uint32_t b1) {
    asm volatile(
        "mma.sync.aligned.m16n8k32.row.col.s32.s8.s8.s32 "
        "{%0,%1,%2,%3}, {%4,%5,%6,%7}, {%8,%9}, {%0,%1,%2,%3};\n"
        : "+r"(c[0]), "+r"(c[1]), "+r"(c[2]), "+r"(c[3])
        : "r"(a[0]), "r"(a[1]), "r"(a[2]), "r"(a[3]), "r"(b0), "r"(b1));
}

__device__ __forceinline__ float comb(int H, int M) {
    return fmaf(16384.0f, __int2float_rn(H), 128.0f * __int2float_rn(M));
}

__device__ __forceinline__ void quant4(float4 v, float inv, char4& h, char4& l) {
    float q0 = fminf(fmaxf(rintf(v.x * inv), -QMAX), QMAX);
    float q1 = fminf(fmaxf(rintf(v.y * inv), -QMAX), QMAX);
    float q2 = fminf(fmaxf(rintf(v.z * inv), -QMAX), QMAX);
    float q3 = fminf(fmaxf(rintf(v.w * inv), -QMAX), QMAX);
    float h0 = rintf(q0 * 0.0078125f), h1 = rintf(q1 * 0.0078125f);
    float h2 = rintf(q2 * 0.0078125f), h3 = rintf(q3 * 0.0078125f);
    h = make_char4((signed char)(int)h0, (signed char)(int)h1,
                   (signed char)(int)h2, (signed char)(int)h3);
    l = make_char4((signed char)(int)(q0 - 128.0f * h0), (signed char)(int)(q1 - 128.0f * h1),
                   (signed char)(int)(q2 - 128.0f * h2), (signed char)(int)(q3 - 128.0f * h3));
}

// warp-cooperative row quantizer (ncols elements, fp32 src)
__device__ __forceinline__ void qrow(const float* __restrict__ src, int ncols, int lane,
                                     float* scale_out, int8_t* dsth, int8_t* dstl) {
    const float4* s4 = (const float4*)src;
    float mx = 0.0f;
    for (int i = lane; i < ncols / 4; i += 32) {
        float4 v = s4[i];
        mx = fmaxf(mx, fmaxf(fmaxf(fabsf(v.x), fabsf(v.y)), fmaxf(fabsf(v.z), fabsf(v.w))));
    }
#pragma unroll
    for (int o = 16; o; o >>= 1) mx = fmaxf(mx, __shfl_xor_sync(0xffffffffu, mx, o));
    mx = fmaxf(mx, 1e-30f);
    float inv = QMAX / mx;
    if (lane == 0) *scale_out = mx / QMAX;
    char4* dh = (char4*)dsth;
    char4* dl = (char4*)dstl;
    for (int i = lane; i < ncols / 4; i += 32) {
        char4 h, l;
        quant4(s4[i], inv, h, l);
        dh[i] = h;
        dl[i] = l;
    }
}

// ---------------- small kernels ----------------
__global__ void k_clear(float* __restrict__ out, int n) {
    int i = blockIdx.x * 256 + threadIdx.x;
    if (i < n) out[i] = 0.0f;
    if (i < HM_ROWS) g_hmax[i] = 0u;
}

__global__ void k_route(const int* __restrict__ rt, const float* __restrict__ rw) {
    __shared__ int scnt[NE], scur[NE];
    int tid = threadIdx.x;
    if (tid < NE) scnt[tid] = 0;
    __syncthreads();
    for (int t = tid; t < T_TOK; t += 256) {
        atomicAdd(&scnt[rt[2 * t]], 1);
        atomicAdd(&scnt[rt[2 * t + 1]], 1);
    }
    __syncthreads();
    if (tid == 0) {
        int base = 0, nt = 0;
        for (int e = 0; e < NE; ++e) {
            int c = scnt[e];
            g_cnt[e] = c;
            g_base[e] = base;
            for (int m0 = 0; m0 < c; m0 += 128) {
                g_tile_e[nt] = e;
                g_tile_m[nt] = m0;
                nt++;
            }
            base += (c + 127) / 128 * 128;
        }
        g_ntiles = nt;
    }
    if (tid < NE) scur[tid] = 0;
    __syncthreads();
    for (int t = tid; t < T_TOK; t += 256) {
#pragma unroll
        for (int k = 0; k < 2; ++k) {
            int e = rt[2 * t + k];
            int p = atomicAdd(&scur[e], 1);
            g_tok[e * LISTCAP + p]  = t;
            g_coef[e * LISTCAP + p] = rw[2 * t + k];
        }
    }
}

// one kernel quantizes X (blocks [0,1024)), permuted W13 ([1024,9216)), W2 ([9216,11264))
__global__ void k_qall(const float* __restrict__ x, const float* __restrict__ w13,
                       const float* __restrict__ w2) {
    int wrow = blockIdx.x * 8 + (threadIdx.x >> 5);
    int lane = threadIdx.x & 31;
    if (blockIdx.x < 1024) {
        int row = wrow;                                     // 0..8191
        qrow(x + (size_t)row * H_DIM, H_DIM, lane, &g_sx[row],
             g_qxh + (size_t)row * H_DIM, g_qxl + (size_t)row * H_DIM);
    } else if (blockIdx.x < 9216) {
        int row = wrow - 8192;                              // 0..65535 permuted
        int e = row >> 13, n = row & 8191;
        int j = n >> 1;
        int srcrow = (n & 1) ? (I_DIM + j) : j;
        qrow(w13 + ((size_t)e * 2 * I_DIM + srcrow) * H_DIM, H_DIM, lane, &g_sw13[row],
             g_qw13h + (size_t)row * H_DIM, g_qw13l + (size_t)row * H_DIM);
    } else {
        int row = wrow - 73728;                             // 0..16383
        qrow(w2 + (size_t)row * I_DIM, I_DIM, lane, &g_sw2[row],
             g_qw2h + (size_t)row * I_DIM, g_qw2l + (size_t)row * I_DIM);
    }
}

// quantize Hm using per-row max gathered by gemm1's atomicMax
__global__ void k_qhm() {
    int row = blockIdx.x * 8 + (threadIdx.x >> 5);
    int lane = threadIdx.x & 31;
    float mx = fmaxf(__uint_as_float(g_hmax[row]), 1e-30f);
    float inv = QMAX / mx;
    if (lane == 0) g_shm[row] = mx / QMAX;
    const float4* src = (const float4*)(g_hm + (size_t)row * I_DIM);
    char4* dh = (char4*)(g_hmh + (size_t)row * I_DIM);
    char4* dl = (char4*)(g_hml + (size_t)row * I_DIM);
    for (int i = lane; i < I_DIM / 4; i += 32) {
        char4 h, l;
        quant4(src[i], inv, h, l);
        dh[i] = h;
        dl[i] = l;
    }
}

// ---------------- int8 fragment compute core (one K=32 stage) ----------------
// 16 warps: warp_m = wid&3 (32 rows), warp_n = wid>>2 (32 cols)
__device__ __forceinline__ void compute_stage(uint32_t st, int warp_m, int warp_n, int lane,
                                              int (&aH)[2][4][4], int (&aM)[2][4][4]) {
    const int rsel = lane & 15;
    const int csel = lane >> 4;
    uint32_t bh[2][4], bl[2][4];
#pragma unroll
    for (int p = 0; p < 2; ++p) {
        uint32_t b = st + OFF_BH + SWZ16(warp_n * 32 + p * 16 + rsel, csel);
        ldsm4(bh[p], b);
        ldsm4(bl[p], b + (OFF_BL - OFF_BH));
    }
#pragma unroll
    for (int mf = 0; mf < 2; ++mf) {
        uint32_t ah[4], al[4];
        uint32_t a = st + SWZ16(warp_m * 32 + mf * 16 + rsel, csel);
        ldsm4(ah, a);
        ldsm4(al, a + OFF_AL);
#pragma unroll
        for (int p = 0; p < 2; ++p)
#pragma unroll
            for (int s = 0; s < 2; ++s) {
                int nf = p * 2 + s;
                mma8(aH[mf][nf], ah, bh[p][s], bh[p][s + 2]);
                mma8(aM[mf][nf], ah, bl[p][s], bl[p][s + 2]);
                mma8(aM[mf][nf], al, bh[p][s], bh[p][s + 2]);
            }
    }
}

// ---------------- GEMM1: Xq[gathered] @ W13q^T, SwiGLU -> f32 Hm + row max ------
__global__ __launch_bounds__(512, 1) void k_gemm1() {
    __shared__ __align__(128) char smem[3 * STB];

    const int tid = threadIdx.x, lane = tid & 31, wid = tid >> 5;
    const int warp_m = wid & 3, warp_n = wid >> 2;

    const int tile = blockIdx.y;
    if (tile >= g_ntiles) return;
    const int e   = g_tile_e[tile];
    const int m0  = g_tile_m[tile];
    const int n0  = blockIdx.x * 128;          // over 8192 permuted rows
    const int cnt = g_cnt[e];
    const int* tokp = g_tok + e * LISTCAP;

    // cp.async: thread -> one row (r=tid>>2) of one plane (sel=tid&3), 2x16B
    const int r = tid >> 2, sel = tid & 3;
    int m = m0 + r;
    int tok = (m < cnt) ? tokp[m] : tokp[0];
    const int8_t* srcp;
    if (sel == 0)      srcp = g_qxh + (size_t)tok * H_DIM;
    else if (sel == 1) srcp = g_qxl + (size_t)tok * H_DIM;
    else if (sel == 2) srcp = g_qw13h + ((size_t)e * 2 * I_DIM + n0 + r) * H_DIM;
    else               srcp = g_qw13l + ((size_t)e * 2 * I_DIM + n0 + r) * H_DIM;

    const uint32_t sb = smem_u32(smem);
    const uint32_t pb = (uint32_t)sel * 4096;
    const uint32_t d0 = pb + SWZ16(r, 0);
    const uint32_t d1 = pb + SWZ16(r, 1);

#define G_ISSUE(it)                                                          \
    do {                                                                     \
        uint32_t b_ = sb + ((it) % 3) * STB;                                 \
        const int8_t* s_ = srcp + (it) * 32;                                 \
        CP16(b_ + d0, s_);                                                   \
        CP16(b_ + d1, s_ + 16);                                              \
        CP_COMMIT();                                                         \
    } while (0)

    int aH[2][4][4], aM[2][4][4];
#pragma unroll
    for (int a = 0; a < 2; ++a)
#pragma unroll
        for (int b = 0; b < 4; ++b)
#pragma unroll
            for (int d = 0; d < 4; ++d) { aH[a][b][d] = 0; aM[a][b][d] = 0; }

    const int KT = H_DIM / 32;   // 64
    G_ISSUE(0);
    G_ISSUE(1);
#pragma unroll 1
    for (int it = 0; it < KT; ++it) {
        if (it < KT - 1) CP_WAIT1(); else CP_WAIT0();
        __syncthreads();
        if (it + 2 < KT) G_ISSUE(it + 2);
        compute_stage(sb + (it % 3) * STB, warp_m, warp_n, lane, aH, aM);
    }

    // epilogue: dequant, SwiGLU, write f32 Hm, track row max
    const int gq = lane >> 2, t4 = lane & 3;
    const int rowbase = g_base[e] + m0;
#pragma unroll
    for (int mf = 0; mf < 2; ++mf) {
        int rl = warp_m * 32 + mf * 16 + gq;
        float sxr[2], hmax2[2] = {0.0f, 0.0f};
#pragma unroll
        for (int hh = 0; hh < 2; ++hh) {
            int mm = m0 + rl + 8 * hh;
            int tk = (mm < cnt) ? tokp[mm] : tokp[0];
            sxr[hh] = g_sx[tk];
        }
#pragma unroll
        for (int nf = 0; nf < 4; ++nf) {
            int pn = n0 + warp_n * 32 + nf * 8 + 2 * t4;
            float swg = g_sw13[e * 8192 + pn];
            float swu = g_sw13[e * 8192 + pn + 1];
            int j = pn >> 1;
#pragma unroll
            for (int hh = 0; hh < 2; ++hh) {
                float gg = sxr[hh] * swg * comb(aH[mf][nf][2 * hh], aM[mf][nf][2 * hh]);
                float uu = sxr[hh] * swu * comb(aH[mf][nf][2 * hh + 1], aM[mf][nf][2 * hh + 1]);
                float hv = uu * gg / (1.0f + __expf(-gg));
                g_hm[(size_t)(rowbase + rl + 8 * hh) * I_DIM + j] = hv;
                hmax2[hh] = fmaxf(hmax2[hh], fabsf(hv));
            }
        }
#pragma unroll
        for (int hh = 0; hh < 2; ++hh) {
            float v = hmax2[hh];
            v = fmaxf(v, __shfl_xor_sync(0xffffffffu, v, 1));
            v = fmaxf(v, __shfl_xor_sync(0xffffffffu, v, 2));
            if (t4 == 0) atomicMax(&g_hmax[rowbase + rl + 8 * hh], __float_as_uint(v));
        }
    }
#undef G_ISSUE
}

// ---------------- GEMM2: Hmq @ W2q^T, coef-scaled atomic scatter -> out ---------
__global__ __launch_bounds__(512, 1) void k_gemm2(float* __restrict__ out) {
    __shared__ __align__(128) char smem[3 * STB];

    const int tid = threadIdx.x, lane = tid & 31, wid = tid >> 5;
    const int warp_m = wid & 3, warp_n = wid >> 2;

    const int tile = blockIdx.y;
    if (tile >= g_ntiles) return;
    const int e   = g_tile_e[tile];
    const int m0  = g_tile_m[tile];
    const int n0  = blockIdx.x * 128;          // over H_DIM
    const int cnt = g_cnt[e];
    const int rb  = g_base[e];

    const int r = tid >> 2, sel = tid & 3;
    const int8_t* srcp;
    if (sel == 0)      srcp = g_hmh + (size_t)(rb + m0 + r) * I_DIM;
    else if (sel == 1) srcp = g_hml + (size_t)(rb + m0 + r) * I_DIM;
    else if (sel == 2) srcp = g_qw2h + ((size_t)e * H_DIM + n0 + r) * I_DIM;
    else               srcp = g_qw2l + ((size_t)e * H_DIM + n0 + r) * I_DIM;

    const uint32_t sb = smem_u32(smem);
    const uint32_t pb = (uint32_t)sel * 4096;
    const uint32_t d0 = pb + SWZ16(r, 0);
    const uint32_t d1 = pb + SWZ16(r, 1);

#define G_ISSUE(it)                                                          \
    do {                                                                     \
        uint32_t b_ = sb + ((it) % 3) * STB;                                 \
        const int8_t* s_ = srcp + (it) * 32;                                 \
        CP16(b_ + d0, s_);                                                   \
        CP16(b_ + d1, s_ + 16);                                              \
        CP_COMMIT();                                                         \
    } while (0)

    int aH[2][4][4], aM[2][4][4];
#pragma unroll
    for (int a = 0; a < 2; ++a)
#pragma unroll
        for (int b = 0; b < 4; ++b)
#pragma unroll
            for (int d = 0; d < 4; ++d) { aH[a][b][d] = 0; aM[a][b][d] = 0; }

    const int KT = I_DIM / 32;   // 128
    G_ISSUE(0);
    G_ISSUE(1);
#pragma unroll 1
    for (int it = 0; it < KT; ++it) {
        if (it < KT - 1) CP_WAIT1(); else CP_WAIT0();
        __syncthreads();
        if (it + 2 < KT) G_ISSUE(it + 2);
        compute_stage(sb + (it % 3) * STB, warp_m, warp_n, lane, aH, aM);
    }

    // epilogue: dequant, coef-scaled atomic scatter
    const int gq = lane >> 2, t4 = lane & 3;
    const int* tokp = g_tok + e * LISTCAP;
    const float* cfp = g_coef + e * LISTCAP;
#pragma unroll
    for (int mf = 0; mf < 2; ++mf) {
        int rl = warp_m * 32 + mf * 16 + gq;
#pragma unroll
        for (int hh = 0; hh < 2; ++hh) {
            int mm = m0 + rl + 8 * hh;
            if (mm < cnt) {
                int tok  = tokp[mm];
                float cs = cfp[mm] * g_shm[rb + mm];
                float* orow = out + (size_t)tok * H_DIM;
#pragma unroll
                for (int nf = 0; nf < 4; ++nf) {
                    int col = n0 + warp_n * 32 + nf * 8 + 2 * t4;
                    float s0 = g_sw2[e * H_DIM + col];
                    float s1 = g_sw2[e * H_DIM + col + 1];
                    atomicAdd(&orow[col],
                              cs * s0 * comb(aH[mf][nf][2 * hh], aM[mf][nf][2 * hh]));
                    atomicAdd(&orow[col + 1],
                              cs * s1 * comb(aH[mf][nf][2 * hh + 1], aM[mf][nf][2 * hh + 1]));
                }
            }
        }
    }
#undef G_ISSUE
}

// --------------------------------------------------------------------------
extern "C" void kernel_launch(void* const* d_in, const int* in_sizes, int n_in,
                              void* d_out, int out_size) {
    const float* x   = (const float*)d_in[0];
    const int*   rt  = (const int*)d_in[1];
    const float* rw  = (const float*)d_in[2];
    const float* w13 = (const float*)d_in[3];
    const float* w2  = (const float*)d_in[4];
    float* out = (float*)d_out;

    const int n = T_TOK * H_DIM;
    k_clear<<<(n + 255) / 256, 256>>>(out, n);                 // my launch 0
    k_route<<<1, 256>>>(rt, rw);                               // my launch 1
    k_qall<<<11264, 256>>>(x, w13, w2);                        // my launch 2
    k_gemm1<<<dim3((2 * I_DIM) / 128, MAXTILES), 512>>>();     // my launch 3 -> profiled
    k_qhm<<<HM_ROWS / 8, 256>>>();                             // my launch 4
    k_gemm2<<<dim3(H_DIM / 128, MAXTILES), 512>>>(out);        // my launch 5
}

// round 10
// speedup vs baseline: 1.3060x; 1.3037x over previous
#include <cuda_runtime.h>
#include <cuda_bf16.h>
#include <cstdint>

#define T_TOK   8192
#define H_DIM   2048
#define I_DIM   4096
#define NE      8
#define LISTCAP 16384
#define MAXT    160
#define HM_ROWS 18432

// ---------------- device scratch (no allocations allowed) ----------------
__device__ int   g_cnt[NE];
__device__ int   g_cur[NE];
__device__ int   g_base[NE];
__device__ int   g_ntiles;
__device__ int   g_tile_e[MAXT];
__device__ int   g_tile_m[MAXT];
__device__ int   g_tok[NE * LISTCAP];
__device__ float g_coef[NE * LISTCAP];
__device__ float g_hm[(size_t)HM_ROWS * I_DIM];   // fp32 intermediate h = silu(g)*u

// ---------------- helpers ----------------
__device__ __forceinline__ void mma_bf16(float* c, const uint32_t* a,
                                         uint32_t b0, uint32_t b1) {
    asm volatile(
        "mma.sync.aligned.m16n8k16.row.col.f32.bf16.bf16.f32 "
        "{%0,%1,%2,%3}, {%4,%5,%6,%7}, {%8,%9}, {%0,%1,%2,%3};\n"
        : "+f"(c[0]), "+f"(c[1]), "+f"(c[2]), "+f"(c[3])
        : "r"(a[0]), "r"(a[1]), "r"(a[2]), "r"(a[3]), "r"(b0), "r"(b1));
}

// fp32 x4 -> packed bf16 hi pair-of-uint2 + lo
__device__ __forceinline__ void split4(float4 v, uint2& hu, uint2& lu) {
    __nv_bfloat162 a, b, c, d;
    a.x = __float2bfloat16(v.x);
    a.y = __float2bfloat16(v.y);
    b.x = __float2bfloat16(v.z);
    b.y = __float2bfloat16(v.w);
    c.x = __float2bfloat16(v.x - __bfloat162float(a.x));
    c.y = __float2bfloat16(v.y - __bfloat162float(a.y));
    d.x = __float2bfloat16(v.z - __bfloat162float(b.x));
    d.y = __float2bfloat16(v.w - __bfloat162float(b.y));
    hu.x = *reinterpret_cast<unsigned*>(&a);
    hu.y = *reinterpret_cast<unsigned*>(&b);
    lu.x = *reinterpret_cast<unsigned*>(&c);
    lu.y = *reinterpret_cast<unsigned*>(&d);
}

// one K=16 slab: warp (wm,wn) computes 32x32 with 3-term bf16 emulated fp32
__device__ __forceinline__ void comp16(
    const __nv_bfloat16 (*sAh)[20], const __nv_bfloat16 (*sAl)[20],
    const __nv_bfloat16 (*sBh)[20], const __nv_bfloat16 (*sBl)[20],
    int wm, int wn, int lane, float (&acc)[2][4][4])
{
    const int gq = lane >> 2, t4 = lane & 3;
    uint32_t bh[4][2], bl[4][2];
#pragma unroll
    for (int nf = 0; nf < 4; ++nf) {
        const __nv_bfloat16* p = &sBh[wn * 32 + nf * 8 + gq][t4 * 2];
        bh[nf][0] = *reinterpret_cast<const uint32_t*>(p);
        bh[nf][1] = *reinterpret_cast<const uint32_t*>(p + 8);
        const __nv_bfloat16* q = &sBl[wn * 32 + nf * 8 + gq][t4 * 2];
        bl[nf][0] = *reinterpret_cast<const uint32_t*>(q);
        bl[nf][1] = *reinterpret_cast<const uint32_t*>(q + 8);
    }
#pragma unroll
    for (int mf = 0; mf < 2; ++mf) {
        uint32_t ah[4], al[4];
        const __nv_bfloat16* p = &sAh[wm * 32 + mf * 16 + gq][t4 * 2];
        ah[0] = *reinterpret_cast<const uint32_t*>(p);
        ah[1] = *reinterpret_cast<const uint32_t*>(p + 8 * 20);
        ah[2] = *reinterpret_cast<const uint32_t*>(p + 8);
        ah[3] = *reinterpret_cast<const uint32_t*>(p + 8 * 20 + 8);
        const __nv_bfloat16* q = &sAl[wm * 32 + mf * 16 + gq][t4 * 2];
        al[0] = *reinterpret_cast<const uint32_t*>(q);
        al[1] = *reinterpret_cast<const uint32_t*>(q + 8 * 20);
        al[2] = *reinterpret_cast<const uint32_t*>(q + 8);
        al[3] = *reinterpret_cast<const uint32_t*>(q + 8 * 20 + 8);
#pragma unroll
        for (int nf = 0; nf < 4; ++nf) {
            mma_bf16(acc[mf][nf], ah, bh[nf][0], bh[nf][1]);
            mma_bf16(acc[mf][nf], ah, bl[nf][0], bl[nf][1]);
            mma_bf16(acc[mf][nf], al, bh[nf][0], bh[nf][1]);
        }
    }
}

// ---------------- routing ----------------
__global__ void k_clear(float* __restrict__ out, int n) {
    int i = blockIdx.x * 256 + threadIdx.x;
    if (i < n) out[i] = 0.0f;
    if (blockIdx.x == 0 && threadIdx.x < NE) g_cur[threadIdx.x] = 0;
}

__global__ void k_route(const int* __restrict__ rt) {
    __shared__ int scnt[NE];
    int tid = threadIdx.x;
    if (tid < NE) scnt[tid] = 0;
    __syncthreads();
    for (int t = tid; t < T_TOK; t += 256) {
        atomicAdd(&scnt[rt[2 * t]], 1);
        atomicAdd(&scnt[rt[2 * t + 1]], 1);
    }
    __syncthreads();
    if (tid == 0) {
        int base = 0, nt = 0;
        for (int e = 0; e < NE; ++e) {
            int c = scnt[e];
            g_cnt[e] = c;
            g_base[e] = base;
            for (int m0 = 0; m0 < c && nt < MAXT; m0 += 128) {
                g_tile_e[nt] = e;
                g_tile_m[nt] = m0;
                nt++;
            }
            base += (c + 127) / 128 * 128;
        }
        g_ntiles = nt;
    }
}

__global__ void k_fill(const int* __restrict__ rt, const float* __restrict__ rw) {
    int t = blockIdx.x * 256 + threadIdx.x;
    if (t >= T_TOK) return;
#pragma unroll
    for (int k = 0; k < 2; ++k) {
        int e = rt[2 * t + k];
        int p = atomicAdd(&g_cur[e], 1);
        g_tok[e * LISTCAP + p]  = t;
        g_coef[e * LISTCAP + p] = rw[2 * t + k];
    }
}

// ---------------- GEMM1: X[gathered] @ W13^T (gate/up interleaved), SwiGLU -> Hm ----
__global__ __launch_bounds__(256, 2) void k_gemm1(const float* __restrict__ x,
                                                  const float* __restrict__ w13) {
    __shared__ __nv_bfloat16 sAh[128][20], sAl[128][20];
    __shared__ __nv_bfloat16 sBh[64][20],  sBl[64][20];

    const int tid = threadIdx.x, lane = tid & 31, wid = tid >> 5;
    const int wm = wid & 3, wn = wid >> 2;

    const int tile = blockIdx.y;
    if (tile >= g_ntiles) return;
    const int e   = g_tile_e[tile];
    const int m0  = g_tile_m[tile];
    const int j0  = blockIdx.x * 32;          // 32 I-columns per block (64 interleaved)
    const int cnt = g_cnt[e];
    const int* tokp = g_tok + e * LISTCAP;

    // A loader: thread -> row (tid&127), col-half (tid>>7): 2 float4 per slab
    const int r = tid & 127, half = tid >> 7;
    int tok = (m0 + r < cnt) ? tokp[m0 + r] : tokp[0];
    const float* aP = x + (size_t)tok * H_DIM + half * 8;
    // B loader: thread -> interleaved row bn (tid>>2), col4 (tid&3): 1 float4
    const int bn = tid >> 2, bc = tid & 3;
    const int srow = (bn & 1) ? (I_DIM + j0 + (bn >> 1)) : (j0 + (bn >> 1));
    const float* bP = w13 + ((size_t)e * 2 * I_DIM + srow) * H_DIM + bc * 4;

    float acc[2][4][4];
#pragma unroll
    for (int a = 0; a < 2; ++a)
#pragma unroll
        for (int b = 0; b < 4; ++b)
#pragma unroll
            for (int d = 0; d < 4; ++d) acc[a][b][d] = 0.0f;

    float4 av0 = *(const float4*)(aP);
    float4 av1 = *(const float4*)(aP + 4);
    float4 bv  = *(const float4*)(bP);

    const int KT = H_DIM / 16;   // 128
#pragma unroll 1
    for (int it = 0; it < KT; ++it) {
        uint2 hu, lu;
        split4(av0, hu, lu);
        *reinterpret_cast<uint2*>(&sAh[r][half * 8]) = hu;
        *reinterpret_cast<uint2*>(&sAl[r][half * 8]) = lu;
        split4(av1, hu, lu);
        *reinterpret_cast<uint2*>(&sAh[r][half * 8 + 4]) = hu;
        *reinterpret_cast<uint2*>(&sAl[r][half * 8 + 4]) = lu;
        split4(bv, hu, lu);
        *reinterpret_cast<uint2*>(&sBh[bn][bc * 4]) = hu;
        *reinterpret_cast<uint2*>(&sBl[bn][bc * 4]) = lu;
        __syncthreads();
        if (it + 1 < KT) {
            int k0 = (it + 1) * 16;
            av0 = *(const float4*)(aP + k0);
            av1 = *(const float4*)(aP + k0 + 4);
            bv  = *(const float4*)(bP + k0);
        }
        comp16(sAh, sAl, sBh, sBl, wm, wn, lane, acc);
        __syncthreads();
    }

    // epilogue: SwiGLU -> fp32 Hm
    const int gq = lane >> 2, t4 = lane & 3;
    const int rowb = g_base[e] + m0 + wm * 32;
#pragma unroll
    for (int mf = 0; mf < 2; ++mf) {
#pragma unroll
        for (int nf = 0; nf < 4; ++nf) {
            int j = j0 + wn * 16 + nf * 4 + t4;
#pragma unroll
            for (int hh = 0; hh < 2; ++hh) {
                float g = acc[mf][nf][hh * 2];
                float u = acc[mf][nf][hh * 2 + 1];
                float hv = u * g / (1.0f + __expf(-g));
                g_hm[(size_t)(rowb + mf * 16 + gq + 8 * hh) * I_DIM + j] = hv;
            }
        }
    }
}

// ---------------- GEMM2: Hm @ W2^T, coef-scaled atomic scatter -> out ----------
__global__ __launch_bounds__(256, 2) void k_gemm2(const float* __restrict__ w2,
                                                  float* __restrict__ out) {
    __shared__ __nv_bfloat16 sAh[128][20], sAl[128][20];
    __shared__ __nv_bfloat16 sBh[64][20],  sBl[64][20];

    const int tid = threadIdx.x, lane = tid & 31, wid = tid >> 5;
    const int wm = wid & 3, wn = wid >> 2;

    const int tile = blockIdx.y;
    if (tile >= g_ntiles) return;
    const int e   = g_tile_e[tile];
    const int m0  = g_tile_m[tile];
    const int n0  = blockIdx.x * 64;          // 64 H-columns per block
    const int cnt = g_cnt[e];
    const int rb  = g_base[e];

    const int r = tid & 127, half = tid >> 7;
    const float* aP = g_hm + (size_t)(rb + m0 + r) * I_DIM + half * 8;
    const int bn = tid >> 2, bc = tid & 3;
    const float* bP = w2 + ((size_t)e * H_DIM + n0 + bn) * I_DIM + bc * 4;

    float acc[2][4][4];
#pragma unroll
    for (int a = 0; a < 2; ++a)
#pragma unroll
        for (int b = 0; b < 4; ++b)
#pragma unroll
            for (int d = 0; d < 4; ++d) acc[a][b][d] = 0.0f;

    float4 av0 = *(const float4*)(aP);
    float4 av1 = *(const float4*)(aP + 4);
    float4 bv  = *(const float4*)(bP);

    const int KT = I_DIM / 16;   // 256
#pragma unroll 1
    for (int it = 0; it < KT; ++it) {
        uint2 hu, lu;
        split4(av0, hu, lu);
        *reinterpret_cast<uint2*>(&sAh[r][half * 8]) = hu;
        *reinterpret_cast<uint2*>(&sAl[r][half * 8]) = lu;
        split4(av1, hu, lu);
        *reinterpret_cast<uint2*>(&sAh[r][half * 8 + 4]) = hu;
        *reinterpret_cast<uint2*>(&sAl[r][half * 8 + 4]) = lu;
        split4(bv, hu, lu);
        *reinterpret_cast<uint2*>(&sBh[bn][bc * 4]) = hu;
        *reinterpret_cast<uint2*>(&sBl[bn][bc * 4]) = lu;
        __syncthreads();
        if (it + 1 < KT) {
            int k0 = (it + 1) * 16;
            av0 = *(const float4*)(aP + k0);
            av1 = *(const float4*)(aP + k0 + 4);
            bv  = *(const float4*)(bP + k0);
        }
        comp16(sAh, sAl, sBh, sBl, wm, wn, lane, acc);
        __syncthreads();
    }

    // epilogue: coef-scaled scatter (exactly 2 commutative fp32 adds / element)
    const int gq = lane >> 2, t4 = lane & 3;
    const int* tokp = g_tok + e * LISTCAP;
    const float* cfp = g_coef + e * LISTCAP;
#pragma unroll
    for (int mf = 0; mf < 2; ++mf) {
#pragma unroll
        for (int hh = 0; hh < 2; ++hh) {
            int mm = m0 + wm * 32 + mf * 16 + gq + 8 * hh;
            if (mm < cnt) {
                int tok  = tokp[mm];
                float cf = cfp[mm];
                float* orow = out + (size_t)tok * H_DIM;
#pragma unroll
                for (int nf = 0; nf < 4; ++nf) {
                    int col = n0 + wn * 32 + nf * 8 + 2 * t4;
                    atomicAdd(&orow[col],     cf * acc[mf][nf][hh * 2]);
                    atomicAdd(&orow[col + 1], cf * acc[mf][nf][hh * 2 + 1]);
                }
            }
        }
    }
}

// --------------------------------------------------------------------------
extern "C" void kernel_launch(void* const* d_in, const int* in_sizes, int n_in,
                              void* d_out, int out_size) {
    const float* x   = (const float*)d_in[0];
    const int*   rt  = (const int*)d_in[1];
    const float* rw  = (const float*)d_in[2];
    const float* w13 = (const float*)d_in[3];
    const float* w2  = (const float*)d_in[4];
    float* out = (float*)d_out;

    const int n = T_TOK * H_DIM;
    k_clear<<<(n + 255) / 256, 256>>>(out, n);                    // my launch 0
    k_route<<<1, 256>>>(rt);                                      // my launch 1
    k_fill<<<(T_TOK + 255) / 256, 256>>>(rt, rw);                 // my launch 2
    k_gemm1<<<dim3(I_DIM / 32, MAXT), 256>>>(x, w13);             // my launch 3 -> profiled
    k_gemm2<<<dim3(H_DIM / 64, MAXT), 256>>>(w2, out);            // my launch 4
}

// round 11
// speedup vs baseline: 1.6224x; 1.2423x over previous
#include <cuda_runtime.h>
#include <cuda_bf16.h>
#include <cstdint>

#define T_TOK   8192
#define H_DIM   2048
#define I_DIM   4096
#define NE      8
#define LISTCAP 16384
#define MAXT    160
#define HM_ROWS 17536

#define STB     16384          /* stage: Ah|Al|Bh|Bl planes of 4KB (128 rows x 32B) */
#define OFF_AL  4096
#define OFF_BH  8192
#define OFF_BL  12288

// ---------------- device scratch (no allocations allowed) ----------------
__device__ int   g_cnt[NE];
__device__ int   g_base[NE];
__device__ int   g_ntiles;
__device__ int   g_tile_e[MAXT];
__device__ int   g_tile_m[MAXT];
__device__ int   g_tok[NE * LISTCAP];
__device__ float g_coef[NE * LISTCAP];

__device__ __nv_bfloat16 g_xh[(size_t)T_TOK * H_DIM];
__device__ __nv_bfloat16 g_xl[(size_t)T_TOK * H_DIM];
__device__ __nv_bfloat16 g_w13h[(size_t)NE * 2 * I_DIM * H_DIM];   // permuted gate/up
__device__ __nv_bfloat16 g_w13l[(size_t)NE * 2 * I_DIM * H_DIM];
__device__ __nv_bfloat16 g_w2h[(size_t)NE * H_DIM * I_DIM];
__device__ __nv_bfloat16 g_w2l[(size_t)NE * H_DIM * I_DIM];
__device__ __nv_bfloat16 g_hmh[(size_t)HM_ROWS * I_DIM];
__device__ __nv_bfloat16 g_hml[(size_t)HM_ROWS * I_DIM];

// ---------------- helpers ----------------
__device__ __forceinline__ uint32_t smem_u32(const void* p) {
    uint32_t a;
    asm("{ .reg .u64 t; cvta.to.shared.u64 t, %1; cvt.u32.u64 %0, t; }" : "=r"(a) : "l"(p));
    return a;
}

// swizzled offset in a [128 rows][32B] tile: 16B chunk XOR'd with row bit2
#define SWZ16(r, c) ((uint32_t)((r) * 32 + ((((c) ^ (((r) >> 2) & 1))) << 4)))

#define CP16(dst, src) \
    asm volatile("cp.async.cg.shared.global [%0], [%1], 16;" :: "r"(dst), "l"(src))
#define CP_COMMIT() asm volatile("cp.async.commit_group;" ::: "memory")
#define CP_WAIT1()  asm volatile("cp.async.wait_group 1;" ::: "memory")
#define CP_WAIT0()  asm volatile("cp.async.wait_group 0;" ::: "memory")

__device__ __forceinline__ void ldsm4(uint32_t* r, uint32_t addr) {
    asm volatile("ldmatrix.sync.aligned.m8n8.x4.shared.b16 {%0,%1,%2,%3}, [%4];"
                 : "=r"(r[0]), "=r"(r[1]), "=r"(r[2]), "=r"(r[3]) : "r"(addr));
}

__device__ __forceinline__ void mma_bf16(float* c, const uint32_t* a,
                                         uint32_t b0, uint32_t b1) {
    asm volatile(
        "mma.sync.aligned.m16n8k16.row.col.f32.bf16.bf16.f32 "
        "{%0,%1,%2,%3}, {%4,%5,%6,%7}, {%8,%9}, {%0,%1,%2,%3};\n"
        : "+f"(c[0]), "+f"(c[1]), "+f"(c[2]), "+f"(c[3])
        : "r"(a[0]), "r"(a[1]), "r"(a[2]), "r"(a[3]), "r"(b0), "r"(b1));
}

// fp32 x4 -> packed bf16 hi/lo uint2
__device__ __forceinline__ void split4(float4 v, uint2& hu, uint2& lu) {
    __nv_bfloat162 a, b, c, d;
    a.x = __float2bfloat16(v.x);
    a.y = __float2bfloat16(v.y);
    b.x = __float2bfloat16(v.z);
    b.y = __float2bfloat16(v.w);
    c.x = __float2bfloat16(v.x - __bfloat162float(a.x));
    c.y = __float2bfloat16(v.y - __bfloat162float(a.y));
    d.x = __float2bfloat16(v.z - __bfloat162float(b.x));
    d.y = __float2bfloat16(v.w - __bfloat162float(b.y));
    hu.x = *reinterpret_cast<unsigned*>(&a);
    hu.y = *reinterpret_cast<unsigned*>(&b);
    lu.x = *reinterpret_cast<unsigned*>(&c);
    lu.y = *reinterpret_cast<unsigned*>(&d);
}

// warp-cooperative row split
__device__ __forceinline__ void srow(const float* __restrict__ src, int n4, int lane,
                                     __nv_bfloat16* dh, __nv_bfloat16* dl) {
    const float4* s4 = (const float4*)src;
    uint2* dh2 = (uint2*)dh;
    uint2* dl2 = (uint2*)dl;
    for (int i = lane; i < n4; i += 32) {
        uint2 hu, lu;
        split4(s4[i], hu, lu);
        dh2[i] = hu;
        dl2[i] = lu;
    }
}

// ---------------- small kernels ----------------
__global__ void k_clear(float* __restrict__ out, int n) {
    int i = blockIdx.x * 256 + threadIdx.x;
    if (i < n) out[i] = 0.0f;
}

// single block: count + scan + tile list + fill
__global__ void k_route(const int* __restrict__ rt, const float* __restrict__ rw) {
    __shared__ int scnt[NE], scur[NE];
    int tid = threadIdx.x;
    if (tid < NE) scnt[tid] = 0;
    __syncthreads();
    for (int t = tid; t < T_TOK; t += 256) {
        atomicAdd(&scnt[rt[2 * t]], 1);
        atomicAdd(&scnt[rt[2 * t + 1]], 1);
    }
    __syncthreads();
    if (tid == 0) {
        int base = 0, nt = 0;
        for (int e = 0; e < NE; ++e) {
            int c = scnt[e];
            g_cnt[e] = c;
            g_base[e] = base;
            for (int m0 = 0; m0 < c && nt < MAXT; m0 += 128) {
                g_tile_e[nt] = e;
                g_tile_m[nt] = m0;
                nt++;
            }
            base += (c + 127) / 128 * 128;
        }
        g_ntiles = nt;
    }
    if (tid < NE) scur[tid] = 0;
    __syncthreads();
    for (int t = tid; t < T_TOK; t += 256) {
#pragma unroll
        for (int k = 0; k < 2; ++k) {
            int e = rt[2 * t + k];
            int p = atomicAdd(&scur[e], 1);
            g_tok[e * LISTCAP + p]  = t;
            g_coef[e * LISTCAP + p] = rw[2 * t + k];
        }
    }
}

// one kernel splits X ([0,1024) blocks), permuted W13 ([1024,9216)), W2 ([9216,11264))
__global__ void k_splitall(const float* __restrict__ x, const float* __restrict__ w13,
                           const float* __restrict__ w2) {
    int wrow = blockIdx.x * 8 + (threadIdx.x >> 5);
    int lane = threadIdx.x & 31;
    if (blockIdx.x < 1024) {
        int row = wrow;                                     // 0..8191
        srow(x + (size_t)row * H_DIM, H_DIM / 4, lane,
             g_xh + (size_t)row * H_DIM, g_xl + (size_t)row * H_DIM);
    } else if (blockIdx.x < 9216) {
        int row = wrow - 8192;                              // 0..65535 permuted
        int e = row >> 13, n = row & 8191;
        int j = n >> 1;
        int srcrow = (n & 1) ? (I_DIM + j) : j;
        srow(w13 + ((size_t)e * 2 * I_DIM + srcrow) * H_DIM, H_DIM / 4, lane,
             g_w13h + (size_t)row * H_DIM, g_w13l + (size_t)row * H_DIM);
    } else {
        int row = wrow - 73728;                             // 0..16383
        srow(w2 + (size_t)row * I_DIM, I_DIM / 4, lane,
             g_w2h + (size_t)row * I_DIM, g_w2l + (size_t)row * I_DIM);
    }
}

// ---------------- bf16 3-term fragment core (one K=16 stage) ----------------
// 16 warps: warp_m = wid&3 (32 rows), warp_n = wid>>2 (32 cols)
__device__ __forceinline__ void compute_stage(uint32_t st, int wm, int wn, int lane,
                                              float (&acc)[2][4][4]) {
    const int rsel = lane & 15;
    const int csel = lane >> 4;
    uint32_t bh[2][4], bl[2][4];
#pragma unroll
    for (int p = 0; p < 2; ++p) {
        uint32_t b = st + OFF_BH + SWZ16(wn * 32 + p * 16 + rsel, csel);
        ldsm4(bh[p], b);
        ldsm4(bl[p], b + (OFF_BL - OFF_BH));
    }
#pragma unroll
    for (int mf = 0; mf < 2; ++mf) {
        uint32_t ah[4], al[4];
        uint32_t a = st + SWZ16(wm * 32 + mf * 16 + rsel, csel);
        ldsm4(ah, a);
        ldsm4(al, a + OFF_AL);
#pragma unroll
        for (int p = 0; p < 2; ++p)
#pragma unroll
            for (int s = 0; s < 2; ++s) {
                int nf = p * 2 + s;
                mma_bf16(acc[mf][nf], ah, bh[p][s], bh[p][s + 2]);
                mma_bf16(acc[mf][nf], ah, bl[p][s], bl[p][s + 2]);
                mma_bf16(acc[mf][nf], al, bh[p][s], bh[p][s + 2]);
            }
    }
}

// ---------------- GEMM1: Xs[gathered] @ W13s^T, SwiGLU -> split bf16 Hm ----------
__global__ __launch_bounds__(512, 1) void k_gemm1() {
    __shared__ __align__(128) char smem[3 * STB];

    const int tid = threadIdx.x, lane = tid & 31, wid = tid >> 5;
    const int wm = wid & 3, wn = wid >> 2;

    const int tile = blockIdx.y;
    if (tile >= g_ntiles) return;
    const int e   = g_tile_e[tile];
    const int m0  = g_tile_m[tile];
    const int n0  = blockIdx.x * 128;          // over 8192 permuted rows
    const int cnt = g_cnt[e];
    const int* tokp = g_tok + e * LISTCAP;

    // cp.async: thread -> row r of plane sel, 2x16B per stage
    const int r = tid >> 2, sel = tid & 3;
    int tok = (m0 + r < cnt) ? tokp[m0 + r] : tokp[0];
    const __nv_bfloat16* srcp;
    if (sel == 0)      srcp = g_xh + (size_t)tok * H_DIM;
    else if (sel == 1) srcp = g_xl + (size_t)tok * H_DIM;
    else if (sel == 2) srcp = g_w13h + ((size_t)e * 2 * I_DIM + n0 + r) * H_DIM;
    else               srcp = g_w13l + ((size_t)e * 2 * I_DIM + n0 + r) * H_DIM;

    const uint32_t sb = smem_u32(smem);
    const uint32_t pb = (uint32_t)sel * 4096;
    const uint32_t d0 = pb + SWZ16(r, 0);
    const uint32_t d1 = pb + SWZ16(r, 1);

#define G_ISSUE(it)                                                          \
    do {                                                                     \
        uint32_t b_ = sb + ((it) % 3) * STB;                                 \
        const __nv_bfloat16* s_ = srcp + (it) * 16;                          \
        CP16(b_ + d0, s_);                                                   \
        CP16(b_ + d1, s_ + 8);                                               \
        CP_COMMIT();                                                         \
    } while (0)

    float acc[2][4][4];
#pragma unroll
    for (int a = 0; a < 2; ++a)
#pragma unroll
        for (int b = 0; b < 4; ++b)
#pragma unroll
            for (int d = 0; d < 4; ++d) acc[a][b][d] = 0.0f;

    const int KT = H_DIM / 16;   // 128
    G_ISSUE(0);
    G_ISSUE(1);
#pragma unroll 1
    for (int it = 0; it < KT; ++it) {
        if (it < KT - 1) CP_WAIT1(); else CP_WAIT0();
        __syncthreads();
        if (it + 2 < KT) G_ISSUE(it + 2);
        compute_stage(sb + (it % 3) * STB, wm, wn, lane, acc);
    }

    // epilogue: SwiGLU -> split bf16 Hm (gate even / up odd interleave)
    const int gq = lane >> 2, t4 = lane & 3;
    const int rowbase = g_base[e] + m0;
#pragma unroll
    for (int mf = 0; mf < 2; ++mf) {
#pragma unroll
        for (int nf = 0; nf < 4; ++nf) {
            int pn = n0 + wn * 32 + nf * 8 + 2 * t4;
            int j = pn >> 1;
#pragma unroll
            for (int hh = 0; hh < 2; ++hh) {
                float g = acc[mf][nf][2 * hh];
                float u = acc[mf][nf][2 * hh + 1];
                float hv = u * g / (1.0f + __expf(-g));
                int row = rowbase + wm * 32 + mf * 16 + gq + 8 * hh;
                __nv_bfloat16 hi = __float2bfloat16(hv);
                __nv_bfloat16 lo = __float2bfloat16(hv - __bfloat162float(hi));
                g_hmh[(size_t)row * I_DIM + j] = hi;
                g_hml[(size_t)row * I_DIM + j] = lo;
            }
        }
    }
#undef G_ISSUE
}

// ---------------- GEMM2: Hms @ W2s^T, coef-scaled atomic scatter -> out ---------
__global__ __launch_bounds__(512, 1) void k_gemm2(float* __restrict__ out) {
    __shared__ __align__(128) char smem[3 * STB];

    const int tid = threadIdx.x, lane = tid & 31, wid = tid >> 5;
    const int wm = wid & 3, wn = wid >> 2;

    const int tile = blockIdx.y;
    if (tile >= g_ntiles) return;
    const int e   = g_tile_e[tile];
    const int m0  = g_tile_m[tile];
    const int n0  = blockIdx.x * 128;          // over H_DIM
    const int cnt = g_cnt[e];
    const int rb  = g_base[e];

    const int r = tid >> 2, sel = tid & 3;
    const __nv_bfloat16* srcp;
    if (sel == 0)      srcp = g_hmh + (size_t)(rb + m0 + r) * I_DIM;
    else if (sel == 1) srcp = g_hml + (size_t)(rb + m0 + r) * I_DIM;
    else if (sel == 2) srcp = g_w2h + ((size_t)e * H_DIM + n0 + r) * I_DIM;
    else               srcp = g_w2l + ((size_t)e * H_DIM + n0 + r) * I_DIM;

    const uint32_t sb = smem_u32(smem);
    const uint32_t pb = (uint32_t)sel * 4096;
    const uint32_t d0 = pb + SWZ16(r, 0);
    const uint32_t d1 = pb + SWZ16(r, 1);

#define G_ISSUE(it)                                                          \
    do {                                                                     \
        uint32_t b_ = sb + ((it) % 3) * STB;                                 \
        const __nv_bfloat16* s_ = srcp + (it) * 16;                          \
        CP16(b_ + d0, s_);                                                   \
        CP16(b_ + d1, s_ + 8);                                               \
        CP_COMMIT();                                                         \
    } while (0)

    float acc[2][4][4];
#pragma unroll
    for (int a = 0; a < 2; ++a)
#pragma unroll
        for (int b = 0; b < 4; ++b)
#pragma unroll
            for (int d = 0; d < 4; ++d) acc[a][b][d] = 0.0f;

    const int KT = I_DIM / 16;   // 256
    G_ISSUE(0);
    G_ISSUE(1);
#pragma unroll 1
    for (int it = 0; it < KT; ++it) {
        if (it < KT - 1) CP_WAIT1(); else CP_WAIT0();
        __syncthreads();
        if (it + 2 < KT) G_ISSUE(it + 2);
        compute_stage(sb + (it % 3) * STB, wm, wn, lane, acc);
    }

    // epilogue: coef-scaled scatter (exactly 2 commutative fp32 adds / element)
    const int gq = lane >> 2, t4 = lane & 3;
    const int* tokp = g_tok + e * LISTCAP;
    const float* cfp = g_coef + e * LISTCAP;
#pragma unroll
    for (int mf = 0; mf < 2; ++mf) {
#pragma unroll
        for (int hh = 0; hh < 2; ++hh) {
            int mm = m0 + wm * 32 + mf * 16 + gq + 8 * hh;
            if (mm < cnt) {
                int tok  = tokp[mm];
                float cf = cfp[mm];
                float* orow = out + (size_t)tok * H_DIM;
#pragma unroll
                for (int nf = 0; nf < 4; ++nf) {
                    int col = n0 + wn * 32 + nf * 8 + 2 * t4;
                    atomicAdd(&orow[col],     cf * acc[mf][nf][2 * hh]);
                    atomicAdd(&orow[col + 1], cf * acc[mf][nf][2 * hh + 1]);
                }
            }
        }
    }
#undef G_ISSUE
}

// --------------------------------------------------------------------------
extern "C" void kernel_launch(void* const* d_in, const int* in_sizes, int n_in,
                              void* d_out, int out_size) {
    const float* x   = (const float*)d_in[0];
    const int*   rt  = (const int*)d_in[1];
    const float* rw  = (const float*)d_in[2];
    const float* w13 = (const float*)d_in[3];
    const float* w2  = (const float*)d_in[4];
    float* out = (float*)d_out;

    const int n = T_TOK * H_DIM;
    k_clear<<<(n + 255) / 256, 256>>>(out, n);                    // my launch 0
    k_route<<<1, 256>>>(rt, rw);                                  // my launch 1
    k_splitall<<<11264, 256>>>(x, w13, w2);                       // my launch 2
    k_gemm1<<<dim3((2 * I_DIM) / 128, MAXT), 512>>>();            // my launch 3 -> profiled
    k_gemm2<<<dim3(H_DIM / 128, MAXT), 512>>>(out);               // my launch 4
}